// round 1
// baseline (speedup 1.0000x reference)
#include <cuda_runtime.h>

// Correlation cost volume:
// out[b,d,h,w] = mean_c( x[b,c,h,w] * y[b,c,h,w-d] )  for w >= d, else 0.
// Shapes: x,y [8,32,256,512] f32; out [8,48,256,512] f32.

#define BDIM 8
#define CDIM 32
#define HDIM 256
#define WDIM 512
#define MAXD 48

#define WT   256            // w-tile per block
#define DT   16             // d per thread
#define NDQ  (MAXD / DT)    // 3 d-groups
#define NWQ  (WT / 4)       // 64 w-groups (4 w per thread)
#define NTHR (NDQ * NWQ)    // 192 threads
#define YS_W (WT + MAXD)    // 304 floats per y row (48-col halo)

#define SMEM_BYTES ((CDIM * WT + CDIM * YS_W) * sizeof(float))  // 70 KB

__global__ __launch_bounds__(NTHR, 2)
void corr_kernel(const float* __restrict__ x,
                 const float* __restrict__ y,
                 float* __restrict__ out) {
    extern __shared__ float smem[];
    float* xs = smem;                 // [CDIM][WT]
    float* ys = smem + CDIM * WT;     // [CDIM][YS_W]

    const int w0  = blockIdx.x * WT;
    const int h   = blockIdx.y;
    const int b   = blockIdx.z;
    const int tid = threadIdx.x;

    const size_t plane = (size_t)HDIM * WDIM;
    const float* xrow = x + ((size_t)b * CDIM * HDIM + h) * WDIM;  // x[b][0][h][0]
    const float* yrow = y + ((size_t)b * CDIM * HDIM + h) * WDIM;

    // ---- stage x tile: CDIM rows of WT floats (float4, coalesced) ----
    #pragma unroll 4
    for (int i = tid; i < CDIM * (WT / 4); i += NTHR) {
        int c = i / (WT / 4);
        int v = i % (WT / 4);
        float4 val = *reinterpret_cast<const float4*>(xrow + c * plane + w0 + v * 4);
        *reinterpret_cast<float4*>(&xs[c * WT + v * 4]) = val;
    }
    // ---- stage y tile with left halo of MAXD (zero-padded below w=0) ----
    #pragma unroll 4
    for (int i = tid; i < CDIM * (YS_W / 4); i += NTHR) {
        int c = i / (YS_W / 4);
        int v = i % (YS_W / 4);
        int gw = w0 - MAXD + v * 4;   // multiple of 4; if <0, all 4 lanes are <0
        float4 val = make_float4(0.f, 0.f, 0.f, 0.f);
        if (gw >= 0)
            val = *reinterpret_cast<const float4*>(yrow + c * plane + gw);
        *reinterpret_cast<float4*>(&ys[c * YS_W + v * 4]) = val;
    }
    __syncthreads();

    const int wq = tid % NWQ;             // 0..63  -> w = w0 + 4*wq + j
    const int dq = tid / NWQ;             // 0..2   -> d = 16*dq + i
    const int hb = MAXD + 4 * wq - DT * dq;  // 4-aligned; min 16, max 300

    float acc[DT][4];
    #pragma unroll
    for (int i = 0; i < DT; i++)
        #pragma unroll
        for (int j = 0; j < 4; j++) acc[i][j] = 0.f;

    #pragma unroll 8
    for (int c = 0; c < CDIM; c++) {
        const float* xsr = &xs[c * WT];
        const float* ysr = &ys[c * YS_W];

        float4 xv = *reinterpret_cast<const float4*>(&xsr[wq * 4]);
        float xj[4] = {xv.x, xv.y, xv.z, xv.w};

        // y window: indices hb-15 .. hb+3 -> 5 aligned float4 loads from hb-16
        float ya[20];
        #pragma unroll
        for (int k = 0; k < 5; k++) {
            float4 t = *reinterpret_cast<const float4*>(&ysr[hb - 16 + 4 * k]);
            ya[4 * k + 0] = t.x; ya[4 * k + 1] = t.y;
            ya[4 * k + 2] = t.z; ya[4 * k + 3] = t.w;
        }

        #pragma unroll
        for (int i = 0; i < DT; i++)
            #pragma unroll
            for (int j = 0; j < 4; j++)
                acc[i][j] += xj[j] * ya[16 + j - i];   // y[w-d]
    }

    // ---- epilogue: mean over C, zero invalid cols (w < d), coalesced STG.128 ----
    const float scale = 1.0f / (float)CDIM;
    const int wbase = w0 + wq * 4;
    #pragma unroll
    for (int i = 0; i < DT; i++) {
        const int d = dq * DT + i;
        float4 o;
        o.x = (wbase + 0 >= d) ? acc[i][0] * scale : 0.f;
        o.y = (wbase + 1 >= d) ? acc[i][1] * scale : 0.f;
        o.z = (wbase + 2 >= d) ? acc[i][2] * scale : 0.f;
        o.w = (wbase + 3 >= d) ? acc[i][3] * scale : 0.f;
        *reinterpret_cast<float4*>(
            out + (((size_t)b * MAXD + d) * HDIM + h) * WDIM + wbase) = o;
    }
}

extern "C" void kernel_launch(void* const* d_in, const int* in_sizes, int n_in,
                              void* d_out, int out_size) {
    const float* x = (const float*)d_in[0];
    const float* y = (const float*)d_in[1];
    float* out = (float*)d_out;

    cudaFuncSetAttribute(corr_kernel,
                         cudaFuncAttributeMaxDynamicSharedMemorySize,
                         (int)SMEM_BYTES);

    dim3 grid(WDIM / WT, HDIM, BDIM);   // (2, 256, 8) = 4096 blocks
    corr_kernel<<<grid, NTHR, SMEM_BYTES>>>(x, y, out);
}

// round 2
// speedup vs baseline: 1.1657x; 1.1657x over previous
#include <cuda_runtime.h>

// Correlation cost volume:
// out[b,d,h,w] = mean_c( x[b,c,h,w] * y[b,c,h,w-d] )  for w >= d, else 0.
// Shapes: x,y [8,32,256,512] f32; out [8,48,256,512] f32.

#define BDIM 8
#define CDIM 32
#define HDIM 256
#define WDIM 512
#define MAXD 48

#define WT   256            // w-tile per block
#define DT   16             // d per thread
#define NDQ  (MAXD / DT)    // 3 d-groups
#define NWQ  (WT / 4)       // 64 w-groups (4 w per thread)
#define NTHR (NDQ * NWQ)    // 192 threads
#define YS_W (WT + MAXD)    // 304 floats per y row (48-col halo)

#define SMEM_BYTES ((CDIM * WT + CDIM * YS_W) * sizeof(float))  // 70 KB

// Packed dual-FP32 FMA (FFMA2) — ptxas never emits this from C++; it doubles
// FP32 FMA throughput vs 3-reg FFMA (rt 2 -> effectively rt 1 per scalar FMA).
__device__ __forceinline__ float2 ffma2(float2 a, float2 b, float2 c) {
    float2 d;
    asm("fma.rn.f32x2 %0, %1, %2, %3;"
        : "=l"(reinterpret_cast<unsigned long long&>(d))
        : "l"(reinterpret_cast<const unsigned long long&>(a)),
          "l"(reinterpret_cast<const unsigned long long&>(b)),
          "l"(reinterpret_cast<const unsigned long long&>(c)));
    return d;
}

__global__ __launch_bounds__(NTHR, 3)   // cap regs at 113 -> 3 blocks/SM (18 warps)
void corr_kernel(const float* __restrict__ x,
                 const float* __restrict__ y,
                 float* __restrict__ out) {
    extern __shared__ float smem[];
    float* xs = smem;                 // [CDIM][WT]
    float* ys = smem + CDIM * WT;     // [CDIM][YS_W]

    const int w0  = blockIdx.x * WT;
    const int h   = blockIdx.y;
    const int b   = blockIdx.z;
    const int tid = threadIdx.x;

    const size_t plane = (size_t)HDIM * WDIM;
    const float* xrow = x + ((size_t)b * CDIM * HDIM + h) * WDIM;  // x[b][0][h][0]
    const float* yrow = y + ((size_t)b * CDIM * HDIM + h) * WDIM;

    // ---- stage x tile: CDIM rows of WT floats (float4, coalesced) ----
    #pragma unroll 4
    for (int i = tid; i < CDIM * (WT / 4); i += NTHR) {
        int c = i / (WT / 4);
        int v = i % (WT / 4);
        float4 val = *reinterpret_cast<const float4*>(xrow + c * plane + w0 + v * 4);
        *reinterpret_cast<float4*>(&xs[c * WT + v * 4]) = val;
    }
    // ---- stage y tile with left halo of MAXD (zero-padded below w=0) ----
    #pragma unroll 4
    for (int i = tid; i < CDIM * (YS_W / 4); i += NTHR) {
        int c = i / (YS_W / 4);
        int v = i % (YS_W / 4);
        int gw = w0 - MAXD + v * 4;   // multiple of 4; if <0, all 4 lanes are <0
        float4 val = make_float4(0.f, 0.f, 0.f, 0.f);
        if (gw >= 0)
            val = *reinterpret_cast<const float4*>(yrow + c * plane + gw);
        *reinterpret_cast<float4*>(&ys[c * YS_W + v * 4]) = val;
    }
    __syncthreads();

    const int wq = tid % NWQ;             // 0..63  -> w = w0 + 4*wq + j
    const int dq = tid / NWQ;             // 0..2   -> d = 16*dq + i
    const int hb = MAXD + 4 * wq - DT * dq;  // 4-aligned; min 16, max 300

    // acc2[i][0] = (acc for j=0, j=1); acc2[i][1] = (j=2, j=3)
    float2 acc2[DT][2];
    #pragma unroll
    for (int i = 0; i < DT; i++) {
        acc2[i][0] = make_float2(0.f, 0.f);
        acc2[i][1] = make_float2(0.f, 0.f);
    }

    #pragma unroll 4
    for (int c = 0; c < CDIM; c++) {
        const float* xsr = &xs[c * WT];
        const float* ysr = &ys[c * YS_W];

        float4 xv = *reinterpret_cast<const float4*>(&xsr[wq * 4]);
        float2 x01 = make_float2(xv.x, xv.y);
        float2 x23 = make_float2(xv.z, xv.w);

        // y window: ya[s] = ys[c][hb-16+s], s = 0..19, as 10 aligned float2 pairs
        // yp[t] = (ya[2t], ya[2t+1]); loaded via 5 aligned LDS.128.
        float2 yp[10];
        #pragma unroll
        for (int k = 0; k < 5; k++) {
            float4 t = *reinterpret_cast<const float4*>(&ysr[hb - 16 + 4 * k]);
            yp[2 * k + 0] = make_float2(t.x, t.y);
            yp[2 * k + 1] = make_float2(t.z, t.w);
        }

        // acc[i][j] += x[j] * ya[16 + j - i]
        //   pair p=0 needs ya pair starting at s = 16 - i
        //   pair p=1 needs ya pair starting at s = 18 - i
        #pragma unroll
        for (int i = 0; i < DT; i++) {
            float2 ylo, yhi;
            if ((i & 1) == 0) {           // even i: aligned pairs, zero cost
                ylo = yp[(16 - i) >> 1];
                yhi = yp[(18 - i) >> 1];
            } else {                      // odd i: cross-pair construct (MOVs)
                ylo = make_float2(yp[(15 - i) >> 1].y, yp[(17 - i) >> 1].x);
                yhi = make_float2(yp[(17 - i) >> 1].y, yp[(19 - i) >> 1].x);
            }
            acc2[i][0] = ffma2(x01, ylo, acc2[i][0]);
            acc2[i][1] = ffma2(x23, yhi, acc2[i][1]);
        }
    }

    // ---- epilogue: mean over C, zero invalid cols (w < d), coalesced STG.128 ----
    const float scale = 1.0f / (float)CDIM;
    const int wbase = w0 + wq * 4;
    #pragma unroll
    for (int i = 0; i < DT; i++) {
        const int d = dq * DT + i;
        float4 o;
        o.x = (wbase + 0 >= d) ? acc2[i][0].x * scale : 0.f;
        o.y = (wbase + 1 >= d) ? acc2[i][0].y * scale : 0.f;
        o.z = (wbase + 2 >= d) ? acc2[i][1].x * scale : 0.f;
        o.w = (wbase + 3 >= d) ? acc2[i][1].y * scale : 0.f;
        *reinterpret_cast<float4*>(
            out + (((size_t)b * MAXD + d) * HDIM + h) * WDIM + wbase) = o;
    }
}

extern "C" void kernel_launch(void* const* d_in, const int* in_sizes, int n_in,
                              void* d_out, int out_size) {
    const float* x = (const float*)d_in[0];
    const float* y = (const float*)d_in[1];
    float* out = (float*)d_out;

    cudaFuncSetAttribute(corr_kernel,
                         cudaFuncAttributeMaxDynamicSharedMemorySize,
                         (int)SMEM_BYTES);

    dim3 grid(WDIM / WT, HDIM, BDIM);   // (2, 256, 8) = 4096 blocks
    corr_kernel<<<grid, NTHR, SMEM_BYTES>>>(x, y, out);
}